// round 8
// baseline (speedup 1.0000x reference)
#include <cuda_runtime.h>
#include <math.h>

#define NN 16384
#define GG 128
#define E0C 262144
#define KK 8

typedef unsigned long long ull;

// ---------------- scratch (device globals; no allocations allowed) ----------
__device__ float g_h1[NN * 16];
__device__ float g_h2[NN * 8];
__device__ int   g_knn[NN * KK];
__device__ float g_h3[NN * 8];
__device__ float g_h4[NN * 16];
__device__ float g_csc[NN * 144];   // per-query candidate scores (2 halves x 72)
__device__ int   g_cix[NN * 144];   // per-query candidate indices

// ---------------- init: zero atomic-max accumulators ------------------------
__global__ void k_init() {
    int i = blockIdx.x * blockDim.x + threadIdx.x;
    if (i < NN * 16) g_h1[i] = 0.0f;
    if (i < NN * 8)  g_h2[i] = 0.0f;
}

// ---------------- conv1: x[N,3] -> h1[N,16] (6->16 relu ->16) ---------------
__global__ void k_conv1(const float* __restrict__ x, const int* __restrict__ ei,
                        const float* __restrict__ w1, const float* __restrict__ b1,
                        const float* __restrict__ w2, const float* __restrict__ b2) {
    __shared__ float sw1[96], sb1[16], sw2[256], sb2[16];
    int t = threadIdx.x;
    for (int v = t; v < 96;  v += blockDim.x) sw1[v] = w1[v];
    for (int v = t; v < 256; v += blockDim.x) sw2[v] = w2[v];
    if (t < 16) { sb1[t] = b1[t]; sb2[t] = b2[t]; }
    __syncthreads();
    int e = blockIdx.x * blockDim.x + t;
    if (e >= E0C) return;
    int s = ei[e], d = ei[E0C + e];
    float xi0 = x[d * 3], xi1 = x[d * 3 + 1], xi2 = x[d * 3 + 2];
    float m[6] = { xi0, xi1, xi2,
                   x[s * 3] - xi0, x[s * 3 + 1] - xi1, x[s * 3 + 2] - xi2 };
    float h[16];
#pragma unroll
    for (int o = 0; o < 16; ++o) h[o] = sb1[o];
#pragma unroll
    for (int i = 0; i < 6; ++i) {
        float mv = m[i];
#pragma unroll
        for (int o = 0; o < 16; ++o) h[o] += mv * sw1[i * 16 + o];
    }
#pragma unroll
    for (int o = 0; o < 16; ++o) h[o] = fmaxf(h[o], 0.0f);
    int* dst = (int*)&g_h1[d * 16];
#pragma unroll
    for (int o = 0; o < 16; ++o) {
        float v = sb2[o];
#pragma unroll
        for (int i = 0; i < 16; ++i) v += h[i] * sw2[i * 16 + o];
        atomicMax(dst + o, __float_as_int(fmaxf(v, 0.0f)));
    }
}

// ---------------- conv2: h1[N,16] -> h2[N,8] (32->8 relu ->8) ---------------
__global__ void k_conv2(const int* __restrict__ ei,
                        const float* __restrict__ w1, const float* __restrict__ b1,
                        const float* __restrict__ w2, const float* __restrict__ b2) {
    __shared__ float sw1[256], sb1[8], sw2[64], sb2[8];
    int t = threadIdx.x;
    for (int v = t; v < 256; v += blockDim.x) sw1[v] = w1[v];
    for (int v = t; v < 64;  v += blockDim.x) sw2[v] = w2[v];
    if (t < 8) { sb1[t] = b1[t]; sb2[t] = b2[t]; }
    __syncthreads();
    int e = blockIdx.x * blockDim.x + t;
    if (e >= E0C) return;
    int s = ei[e], d = ei[E0C + e];
    const float4* Xi = (const float4*)&g_h1[d * 16];
    const float4* Xj = (const float4*)&g_h1[s * 16];
    float xi[16], xj[16];
#pragma unroll
    for (int q = 0; q < 4; ++q) {
        float4 a = Xi[q], b = Xj[q];
        xi[q * 4 + 0] = a.x; xi[q * 4 + 1] = a.y; xi[q * 4 + 2] = a.z; xi[q * 4 + 3] = a.w;
        xj[q * 4 + 0] = b.x; xj[q * 4 + 1] = b.y; xj[q * 4 + 2] = b.z; xj[q * 4 + 3] = b.w;
    }
    float h[8];
#pragma unroll
    for (int o = 0; o < 8; ++o) h[o] = sb1[o];
#pragma unroll
    for (int f = 0; f < 16; ++f) {
        float m0 = xi[f], m1 = xj[f] - xi[f];
#pragma unroll
        for (int o = 0; o < 8; ++o)
            h[o] += m0 * sw1[f * 8 + o] + m1 * sw1[(16 + f) * 8 + o];
    }
#pragma unroll
    for (int o = 0; o < 8; ++o) h[o] = fmaxf(h[o], 0.0f);
    int* dst = (int*)&g_h2[d * 8];
#pragma unroll
    for (int o = 0; o < 8; ++o) {
        float v = sb2[o];
#pragma unroll
        for (int i = 0; i < 8; ++i) v += h[i] * sw2[i * 8 + o];
        atomicMax(dst + o, __float_as_int(fmaxf(v, 0.0f)));
    }
}

// ---------------- kNN --------------------------------------------------------
// Score s = dot(q,p) - 0.5|p|^2 (monotone in -distance; sq_i cancels).
// Grid = 256 query-groups x 2 point-halves = 512 CTAs. Each CTA: 64 queries
// (2 per lane), 8 warps = point slices, scanning its 8192-point half.
// One point's 2 broadcast LDS.128 (+0.25 LDS for a 4-norm quad) feed 64 evals
// (2 independent FFMA chains per lane). Hits do a 2-op push (query tagged in
// idx bit 14) into a per-lane shared stack; exact top-9 maintenance runs only
// in rare whole-warp drains (vote every 2 points -> cnt <= 12, BCAP=12).
// thr staleness only adds pushes, never drops candidates -> exact.
// Candidates (2 halves x 8 slices x 9) dumped to global; k_kmerge does exact
// (score desc, idx asc) selection, skipping self (the provable max score).
#define QBH  64      // queries per block
#define KT   512     // tile points
#define BCAP 12
#define HALFN 8192
#define KNN_SMEM (16384 + 2048 + 256 * BCAP * 8)
static_assert(KNN_SMEM <= 48 * 1024, "static smem limit");

#define INS9(p, _cv, _iv) do {                                                \
    float _c = (_cv); int _i = (_iv);                                         \
    bool _r = (p##s0 == p##thr);        if (_r) { p##s0 = _c; p##i0 = _i; }   \
    bool _n = !_r && (p##s1 == p##thr); if (_n) { p##s1 = _c; p##i1 = _i; } _r |= _n; \
    _n = !_r && (p##s2 == p##thr);      if (_n) { p##s2 = _c; p##i2 = _i; } _r |= _n; \
    _n = !_r && (p##s3 == p##thr);      if (_n) { p##s3 = _c; p##i3 = _i; } _r |= _n; \
    _n = !_r && (p##s4 == p##thr);      if (_n) { p##s4 = _c; p##i4 = _i; } _r |= _n; \
    _n = !_r && (p##s5 == p##thr);      if (_n) { p##s5 = _c; p##i5 = _i; } _r |= _n; \
    _n = !_r && (p##s6 == p##thr);      if (_n) { p##s6 = _c; p##i6 = _i; } _r |= _n; \
    _n = !_r && (p##s7 == p##thr);      if (_n) { p##s7 = _c; p##i7 = _i; } _r |= _n; \
    _n = !_r;                           if (_n) { p##s8 = _c; p##i8 = _i; }   \
    p##thr = fminf(fminf(fminf(fminf(p##s0, p##s1), fminf(p##s2, p##s3)),     \
                         fminf(fminf(p##s4, p##s5), fminf(p##s6, p##s7))), p##s8); \
} while (0)

#define DRAIN() do {                                                          \
    int _m = __reduce_max_sync(0xffffffffu, cnt);                             \
    for (int _e = 0; _e < _m; ++_e) {                                         \
        if (_e < cnt) {                                                       \
            ull _v = mybuf[_e];                                               \
            float _sc = __uint_as_float((unsigned)_v);                        \
            int _id = (int)(_v >> 32);                                        \
            if (_id & 16384) { int _j = _id & 16383;                          \
                if (_sc > bthr) { INS9(b, _sc, _j); } }                       \
            else { if (_sc > athr) { INS9(a, _sc, _id); } }                   \
        }                                                                     \
    }                                                                         \
    cnt = 0;                                                                  \
} while (0)

#define EVAL(_A, _B, _nn, _jj) do {                                           \
    float4 A = (_A); float4 B = (_B); float n = (_nn); int j = (_jj);         \
    float acc0 = fmaf(A.x, q00, fmaf(A.y, q01, fmaf(A.z, q02, fmaf(A.w, q03,  \
                 fmaf(B.x, q04, fmaf(B.y, q05, fmaf(B.z, q06, fmaf(B.w, q07, n)))))))); \
    float acc1 = fmaf(A.x, q10, fmaf(A.y, q11, fmaf(A.z, q12, fmaf(A.w, q13,  \
                 fmaf(B.x, q14, fmaf(B.y, q15, fmaf(B.z, q16, fmaf(B.w, q17, n)))))))); \
    if (acc0 > athr) { mybuf[cnt] = (((ull)(unsigned)j) << 32) | (ull)__float_as_uint(acc0); ++cnt; } \
    if (acc1 > bthr) { mybuf[cnt] = (((ull)(unsigned)(j | 16384)) << 32) | (ull)__float_as_uint(acc1); ++cnt; } \
} while (0)

#define CHK() do { if (__any_sync(0xffffffffu, cnt >= 9)) { DRAIN(); } } while (0)

__global__ void __launch_bounds__(256, 3) k_knn() {
    __shared__ __align__(16) char sbuf[KNN_SMEM];
    float4* sp  = (float4*)sbuf;                 // 512 points x 32B comps
    float*  snm = (float*)(sbuf + 16384);        // 512 norms (-0.5|p|^2)
    ull* bufall = (ull*)(sbuf + 18432);          // per-lane push stacks

    int t = threadIdx.x;
    int w = t >> 5, lane = t & 31;
    int half = blockIdx.x & 1;
    int qb = (blockIdx.x >> 1) * QBH;
    int q0 = qb + lane, q1 = qb + 32 + lane;
    int pbase = half * HALFN;

    ull* mybuf = bufall + t * BCAP;
    int cnt = 0;

    float4 qa = ((const float4*)g_h2)[q0 * 2];
    float4 qc = ((const float4*)g_h2)[q0 * 2 + 1];
    float q00 = qa.x, q01 = qa.y, q02 = qa.z, q03 = qa.w;
    float q04 = qc.x, q05 = qc.y, q06 = qc.z, q07 = qc.w;
    float4 qd = ((const float4*)g_h2)[q1 * 2];
    float4 qe = ((const float4*)g_h2)[q1 * 2 + 1];
    float q10 = qd.x, q11 = qd.y, q12 = qd.z, q13 = qd.w;
    float q14 = qe.x, q15 = qe.y, q16 = qe.z, q17 = qe.w;

    float as0 = -INFINITY, as1 = -INFINITY, as2 = -INFINITY, as3 = -INFINITY,
          as4 = -INFINITY, as5 = -INFINITY, as6 = -INFINITY, as7 = -INFINITY,
          as8 = -INFINITY, athr = -INFINITY;
    int ai0 = 0, ai1 = 0, ai2 = 0, ai3 = 0, ai4 = 0, ai5 = 0, ai6 = 0, ai7 = 0, ai8 = 0;
    float bs0 = -INFINITY, bs1 = -INFINITY, bs2 = -INFINITY, bs3 = -INFINITY,
          bs4 = -INFINITY, bs5 = -INFINITY, bs6 = -INFINITY, bs7 = -INFINITY,
          bs8 = -INFINITY, bthr = -INFINITY;
    int bi0 = 0, bi1 = 0, bi2 = 0, bi3 = 0, bi4 = 0, bi5 = 0, bi6 = 0, bi7 = 0, bi8 = 0;

    for (int tb = 0; tb < HALFN; tb += KT) {
        __syncthreads();
        for (int v = t; v < KT; v += 256) {
            float4 a = ((const float4*)g_h2)[(pbase + tb + v) * 2];
            float4 b = ((const float4*)g_h2)[(pbase + tb + v) * 2 + 1];
            sp[v * 2] = a; sp[v * 2 + 1] = b;
            float sq = a.x * a.x + a.y * a.y + a.z * a.z + a.w * a.w +
                       b.x * b.x + b.y * b.y + b.z * b.z + b.w * b.w;
            snm[v] = -0.5f * sq;
        }
        __syncthreads();
        int base = w << 6;   // this warp's 64-point slice
        for (int g = 0; g < 16; ++g) {
            int p = base + (g << 2);
            float4 nq = *(const float4*)(snm + p);
            int j0 = pbase + tb + p;
            EVAL(sp[(p + 0) * 2], sp[(p + 0) * 2 + 1], nq.x, j0 + 0);
            EVAL(sp[(p + 1) * 2], sp[(p + 1) * 2 + 1], nq.y, j0 + 1);
            CHK();
            EVAL(sp[(p + 2) * 2], sp[(p + 2) * 2 + 1], nq.z, j0 + 2);
            EVAL(sp[(p + 3) * 2], sp[(p + 3) * 2 + 1], nq.w, j0 + 3);
            CHK();
        }
    }
    DRAIN();

    // dump candidates: layout g_csc[q*144 + half*72 + w*9 + r]
    {
        int c = q0 * 144 + half * 72 + w * 9;
        g_csc[c + 0] = as0; g_csc[c + 1] = as1; g_csc[c + 2] = as2;
        g_csc[c + 3] = as3; g_csc[c + 4] = as4; g_csc[c + 5] = as5;
        g_csc[c + 6] = as6; g_csc[c + 7] = as7; g_csc[c + 8] = as8;
        g_cix[c + 0] = ai0; g_cix[c + 1] = ai1; g_cix[c + 2] = ai2;
        g_cix[c + 3] = ai3; g_cix[c + 4] = ai4; g_cix[c + 5] = ai5;
        g_cix[c + 6] = ai6; g_cix[c + 7] = ai7; g_cix[c + 8] = ai8;
        c = q1 * 144 + half * 72 + w * 9;
        g_csc[c + 0] = bs0; g_csc[c + 1] = bs1; g_csc[c + 2] = bs2;
        g_csc[c + 3] = bs3; g_csc[c + 4] = bs4; g_csc[c + 5] = bs5;
        g_csc[c + 6] = bs6; g_csc[c + 7] = bs7; g_csc[c + 8] = bs8;
        g_cix[c + 0] = bi0; g_cix[c + 1] = bi1; g_cix[c + 2] = bi2;
        g_cix[c + 3] = bi3; g_cix[c + 4] = bi4; g_cix[c + 5] = bi5;
        g_cix[c + 6] = bi6; g_cix[c + 7] = bi7; g_cix[c + 8] = bi8;
    }
}

// ---------------- kNN merge: exact top-8 over 144 candidates per query -------
// Candidates are distinct (each point in exactly one half, one slice top-9).
// Selection via descending (score, -idx) lex order with previous-pick bound;
// skip self (present exactly once as the global max).
__global__ void k_kmerge() {
    int q = blockIdx.x * blockDim.x + threadIdx.x;
    if (q >= NN) return;
    const float* cs = g_csc + q * 144;
    const int*   ci = g_cix + q * 144;
    float psc = INFINITY; int pix = -1;   // sentinel: lex-greater than all
    int written = 0;
    for (int pick = 0; pick < 9 && written < 8; ++pick) {
        float bs = -INFINITY; int bi = 0x7fffffff;
        for (int e = 0; e < 144; ++e) {
            float v = cs[e]; int id = ci[e];
            bool lessPrev = (v < psc) || (v == psc && id > pix);
            bool better   = (v > bs)  || (v == bs  && id < bi);
            if (lessPrev && better) { bs = v; bi = id; }
        }
        psc = bs; pix = bi;
        if (bi != q) { g_knn[q * 8 + written] = bi; ++written; }
    }
}

// ---------------- conv3: h2[N,8] -> h3[N,8] over kNN edges (16->8 relu ->8) --
__global__ void k_conv3(const float* __restrict__ w1, const float* __restrict__ b1,
                        const float* __restrict__ w2, const float* __restrict__ b2) {
    __shared__ float sw1[128], sb1[8], sw2[64], sb2[8];
    int t = threadIdx.x;
    for (int v = t; v < 128; v += blockDim.x) sw1[v] = w1[v];
    for (int v = t; v < 64;  v += blockDim.x) sw2[v] = w2[v];
    if (t < 8) { sb1[t] = b1[t]; sb2[t] = b2[t]; }
    __syncthreads();
    int i = blockIdx.x * blockDim.x + t;
    float xi[8];
    {
        float4 a = ((const float4*)g_h2)[i * 2];
        float4 b = ((const float4*)g_h2)[i * 2 + 1];
        xi[0] = a.x; xi[1] = a.y; xi[2] = a.z; xi[3] = a.w;
        xi[4] = b.x; xi[5] = b.y; xi[6] = b.z; xi[7] = b.w;
    }
    float out[8];
#pragma unroll
    for (int o = 0; o < 8; ++o) out[o] = 0.0f;
#pragma unroll
    for (int n = 0; n < 8; ++n) {
        int j = g_knn[i * 8 + n];
        float4 c = ((const float4*)g_h2)[j * 2];
        float4 d = ((const float4*)g_h2)[j * 2 + 1];
        float xj[8] = { c.x, c.y, c.z, c.w, d.x, d.y, d.z, d.w };
        float h[8];
#pragma unroll
        for (int o = 0; o < 8; ++o) h[o] = sb1[o];
#pragma unroll
        for (int f = 0; f < 8; ++f) {
            float m0 = xi[f], m1 = xj[f] - xi[f];
#pragma unroll
            for (int o = 0; o < 8; ++o)
                h[o] += m0 * sw1[f * 8 + o] + m1 * sw1[(8 + f) * 8 + o];
        }
#pragma unroll
        for (int o = 0; o < 8; ++o) h[o] = fmaxf(h[o], 0.0f);
#pragma unroll
        for (int o = 0; o < 8; ++o) {
            float v = sb2[o];
#pragma unroll
            for (int f = 0; f < 8; ++f) v += h[f] * sw2[f * 8 + o];
            out[o] = fmaxf(out[o], v);
        }
    }
#pragma unroll
    for (int o = 0; o < 8; ++o) g_h3[i * 8 + o] = out[o];
}

// ---------------- conv4: h3[N,8] -> h4[N,16] over kNN edges (16->16 relu ->16)
__global__ void k_conv4(const float* __restrict__ w1, const float* __restrict__ b1,
                        const float* __restrict__ w2, const float* __restrict__ b2) {
    __shared__ float sw1[256], sb1[16], sw2[256], sb2[16];
    int t = threadIdx.x;
    for (int v = t; v < 256; v += blockDim.x) { sw1[v] = w1[v]; sw2[v] = w2[v]; }
    if (t < 16) { sb1[t] = b1[t]; sb2[t] = b2[t]; }
    __syncthreads();
    int i = blockIdx.x * blockDim.x + t;
    float xi[8];
    {
        float4 a = ((const float4*)g_h3)[i * 2];
        float4 b = ((const float4*)g_h3)[i * 2 + 1];
        xi[0] = a.x; xi[1] = a.y; xi[2] = a.z; xi[3] = a.w;
        xi[4] = b.x; xi[5] = b.y; xi[6] = b.z; xi[7] = b.w;
    }
    float out[16];
#pragma unroll
    for (int o = 0; o < 16; ++o) out[o] = 0.0f;
#pragma unroll
    for (int n = 0; n < 8; ++n) {
        int j = g_knn[i * 8 + n];
        float4 c = ((const float4*)g_h3)[j * 2];
        float4 d = ((const float4*)g_h3)[j * 2 + 1];
        float xj[8] = { c.x, c.y, c.z, c.w, d.x, d.y, d.z, d.w };
        float h[16];
#pragma unroll
        for (int o = 0; o < 16; ++o) h[o] = sb1[o];
#pragma unroll
        for (int f = 0; f < 8; ++f) {
            float m0 = xi[f], m1 = xj[f] - xi[f];
#pragma unroll
            for (int o = 0; o < 16; ++o)
                h[o] += m0 * sw1[f * 16 + o] + m1 * sw1[(8 + f) * 16 + o];
        }
#pragma unroll
        for (int o = 0; o < 16; ++o) h[o] = fmaxf(h[o], 0.0f);
#pragma unroll
        for (int o = 0; o < 16; ++o) {
            float v = sb2[o];
#pragma unroll
            for (int f = 0; f < 16; ++f) v += h[f] * sw2[f * 16 + o];
            out[o] = fmaxf(out[o], v);
        }
    }
#pragma unroll
    for (int o = 0; o < 16; ++o) g_h4[i * 16 + o] = out[o];
}

// ---------------- global max pool + MLP head + sigmoid -----------------------
__global__ void k_pool(const float* __restrict__ fw, const float* __restrict__ fb,
                       const float* __restrict__ ow, const float* __restrict__ ob,
                       float* __restrict__ out) {
    __shared__ float s[128 * 16];
    int g = blockIdx.x, t = threadIdx.x;
    int node = g * 128 + t;
#pragma unroll
    for (int f = 0; f < 16; ++f) s[t * 16 + f] = g_h4[node * 16 + f];
    __syncthreads();
    for (int st = 64; st > 0; st >>= 1) {
        if (t < st) {
#pragma unroll
            for (int f = 0; f < 16; ++f)
                s[t * 16 + f] = fmaxf(s[t * 16 + f], s[(t + st) * 16 + f]);
        }
        __syncthreads();
    }
    if (t == 0) {
        float z = ob[0];
#pragma unroll
        for (int o = 0; o < 6; ++o) {
            float y = fb[o];
#pragma unroll
            for (int f = 0; f < 16; ++f) y += s[f] * fw[f * 6 + o];
            z += fmaxf(y, 0.0f) * ow[o];
        }
        out[g] = 1.0f / (1.0f + expf(-z));
    }
}

// ---------------- launch ------------------------------------------------------
extern "C" void kernel_launch(void* const* d_in, const int* in_sizes, int n_in,
                              void* d_out, int out_size) {
    const float* x    = (const float*)d_in[0];
    const int*   ei   = (const int*)d_in[1];
    const float* c1w1 = (const float*)d_in[3];
    const float* c1b1 = (const float*)d_in[4];
    const float* c1w2 = (const float*)d_in[5];
    const float* c1b2 = (const float*)d_in[6];
    const float* c2w1 = (const float*)d_in[7];
    const float* c2b1 = (const float*)d_in[8];
    const float* c2w2 = (const float*)d_in[9];
    const float* c2b2 = (const float*)d_in[10];
    const float* c3w1 = (const float*)d_in[11];
    const float* c3b1 = (const float*)d_in[12];
    const float* c3w2 = (const float*)d_in[13];
    const float* c3b2 = (const float*)d_in[14];
    const float* c4w1 = (const float*)d_in[15];
    const float* c4b1 = (const float*)d_in[16];
    const float* c4w2 = (const float*)d_in[17];
    const float* c4b2 = (const float*)d_in[18];
    const float* fc3w = (const float*)d_in[19];
    const float* fc3b = (const float*)d_in[20];
    const float* outw = (const float*)d_in[21];
    const float* outb = (const float*)d_in[22];

    k_init  <<< (NN * 16 + 255) / 256, 256 >>> ();
    k_conv1 <<< E0C / 256, 256 >>>(x, ei, c1w1, c1b1, c1w2, c1b2);
    k_conv2 <<< E0C / 256, 256 >>>(ei, c2w1, c2b1, c2w2, c2b2);
    k_knn   <<< (NN / QBH) * 2, 256 >>>();
    k_kmerge<<< NN / 256, 256 >>>();
    k_conv3 <<< NN / 128, 128 >>>(c3w1, c3b1, c3w2, c3b2);
    k_conv4 <<< NN / 128, 128 >>>(c4w1, c4b1, c4w2, c4b2);
    k_pool  <<< GG, 128 >>>(fc3w, fc3b, outw, outb, (float*)d_out);
}

// round 9
// speedup vs baseline: 1.6227x; 1.6227x over previous
#include <cuda_runtime.h>
#include <math.h>

#define NN 16384
#define GG 128
#define E0C 262144
#define KK 8

typedef unsigned long long ull;

// ---------------- scratch (device globals; no allocations allowed) ----------
__device__ float g_h1[NN * 16];
__device__ float g_h2[NN * 8];
__device__ int   g_knn[NN * KK];
__device__ float g_h3[NN * 8];
__device__ float g_h4[NN * 16];

// ---------------- init: zero atomic-max accumulators ------------------------
__global__ void k_init() {
    int i = blockIdx.x * blockDim.x + threadIdx.x;
    if (i < NN * 16) g_h1[i] = 0.0f;
    if (i < NN * 8)  g_h2[i] = 0.0f;
}

// ---------------- conv1: x[N,3] -> h1[N,16] (6->16 relu ->16) ---------------
__global__ void k_conv1(const float* __restrict__ x, const int* __restrict__ ei,
                        const float* __restrict__ w1, const float* __restrict__ b1,
                        const float* __restrict__ w2, const float* __restrict__ b2) {
    __shared__ float sw1[96], sb1[16], sw2[256], sb2[16];
    int t = threadIdx.x;
    for (int v = t; v < 96;  v += blockDim.x) sw1[v] = w1[v];
    for (int v = t; v < 256; v += blockDim.x) sw2[v] = w2[v];
    if (t < 16) { sb1[t] = b1[t]; sb2[t] = b2[t]; }
    __syncthreads();
    int e = blockIdx.x * blockDim.x + t;
    if (e >= E0C) return;
    int s = ei[e], d = ei[E0C + e];
    float xi0 = x[d * 3], xi1 = x[d * 3 + 1], xi2 = x[d * 3 + 2];
    float m[6] = { xi0, xi1, xi2,
                   x[s * 3] - xi0, x[s * 3 + 1] - xi1, x[s * 3 + 2] - xi2 };
    float h[16];
#pragma unroll
    for (int o = 0; o < 16; ++o) h[o] = sb1[o];
#pragma unroll
    for (int i = 0; i < 6; ++i) {
        float mv = m[i];
#pragma unroll
        for (int o = 0; o < 16; ++o) h[o] += mv * sw1[i * 16 + o];
    }
#pragma unroll
    for (int o = 0; o < 16; ++o) h[o] = fmaxf(h[o], 0.0f);
    int* dst = (int*)&g_h1[d * 16];
#pragma unroll
    for (int o = 0; o < 16; ++o) {
        float v = sb2[o];
#pragma unroll
        for (int i = 0; i < 16; ++i) v += h[i] * sw2[i * 16 + o];
        atomicMax(dst + o, __float_as_int(fmaxf(v, 0.0f)));
    }
}

// ---------------- conv2: h1[N,16] -> h2[N,8] (32->8 relu ->8) ---------------
__global__ void k_conv2(const int* __restrict__ ei,
                        const float* __restrict__ w1, const float* __restrict__ b1,
                        const float* __restrict__ w2, const float* __restrict__ b2) {
    __shared__ float sw1[256], sb1[8], sw2[64], sb2[8];
    int t = threadIdx.x;
    for (int v = t; v < 256; v += blockDim.x) sw1[v] = w1[v];
    for (int v = t; v < 64;  v += blockDim.x) sw2[v] = w2[v];
    if (t < 8) { sb1[t] = b1[t]; sb2[t] = b2[t]; }
    __syncthreads();
    int e = blockIdx.x * blockDim.x + t;
    if (e >= E0C) return;
    int s = ei[e], d = ei[E0C + e];
    const float4* Xi = (const float4*)&g_h1[d * 16];
    const float4* Xj = (const float4*)&g_h1[s * 16];
    float xi[16], xj[16];
#pragma unroll
    for (int q = 0; q < 4; ++q) {
        float4 a = Xi[q], b = Xj[q];
        xi[q * 4 + 0] = a.x; xi[q * 4 + 1] = a.y; xi[q * 4 + 2] = a.z; xi[q * 4 + 3] = a.w;
        xj[q * 4 + 0] = b.x; xj[q * 4 + 1] = b.y; xj[q * 4 + 2] = b.z; xj[q * 4 + 3] = b.w;
    }
    float h[8];
#pragma unroll
    for (int o = 0; o < 8; ++o) h[o] = sb1[o];
#pragma unroll
    for (int f = 0; f < 16; ++f) {
        float m0 = xi[f], m1 = xj[f] - xi[f];
#pragma unroll
        for (int o = 0; o < 8; ++o)
            h[o] += m0 * sw1[f * 8 + o] + m1 * sw1[(16 + f) * 8 + o];
    }
#pragma unroll
    for (int o = 0; o < 8; ++o) h[o] = fmaxf(h[o], 0.0f);
    int* dst = (int*)&g_h2[d * 8];
#pragma unroll
    for (int o = 0; o < 8; ++o) {
        float v = sb2[o];
#pragma unroll
        for (int i = 0; i < 8; ++i) v += h[i] * sw2[i * 8 + o];
        atomicMax(dst + o, __float_as_int(fmaxf(v, 0.0f)));
    }
}

// ---------------- kNN --------------------------------------------------------
// Score s = dot(q,p) - 0.5|p|^2 (monotone in -distance; sq_i cancels).
// Lanes = queries (32/CTA), warps = point slices; point reads are warp-uniform
// broadcasts. Point comps in sp[] (32B records), norms batched 4-per-LDS.128.
// HOT PATH per point: 8 FFMA + guard + 2 predicated push ops. Exact top-9
// maintenance (INS9) runs only in whole-warp drains, vote-checked every 4
// points (cnt <= 8+4 = 12 = BCAP). thr staleness only adds pushes, never
// drops candidates -> exact. Self is the provable global max score -> keep 9,
// drop idx==gq at the in-block merge (R6 structure).
#define QB   32      // queries per block (one per lane)
#define KT   512     // tile points
#define BCAP 12
#define KNN_SMEM (16384 + 2048 + 256 * BCAP * 8)   // 43008
static_assert(KNN_SMEM <= 48 * 1024, "static smem limit");

#define INS9(sc, id) do {                                                     \
    float _c = (sc); int _i = (id);                                           \
    bool _r = (s0 == thr);            if (_r)  { s0 = _c; i0 = _i; }          \
    bool _n = !_r && (s1 == thr);     if (_n)  { s1 = _c; i1 = _i; } _r |= _n;\
    _n = !_r && (s2 == thr);          if (_n)  { s2 = _c; i2 = _i; } _r |= _n;\
    _n = !_r && (s3 == thr);          if (_n)  { s3 = _c; i3 = _i; } _r |= _n;\
    _n = !_r && (s4 == thr);          if (_n)  { s4 = _c; i4 = _i; } _r |= _n;\
    _n = !_r && (s5 == thr);          if (_n)  { s5 = _c; i5 = _i; } _r |= _n;\
    _n = !_r && (s6 == thr);          if (_n)  { s6 = _c; i6 = _i; } _r |= _n;\
    _n = !_r && (s7 == thr);          if (_n)  { s7 = _c; i7 = _i; } _r |= _n;\
    _n = !_r;                         if (_n)  { s8 = _c; i8 = _i; }          \
    thr = fminf(fminf(fminf(fminf(s0, s1), fminf(s2, s3)),                    \
                      fminf(fminf(s4, s5), fminf(s6, s7))), s8);              \
} while (0)

#define DRAIN() do {                                                          \
    int _m = __reduce_max_sync(0xffffffffu, cnt);                             \
    for (int _e = 0; _e < _m; ++_e) {                                         \
        if (_e < cnt) {                                                       \
            ull _v = mybuf[_e];                                               \
            float _sc = __uint_as_float((unsigned)_v);                        \
            int _id = (int)(_v >> 32);                                        \
            if (_sc > thr) { INS9(_sc, _id); }                                \
        }                                                                     \
    }                                                                         \
    cnt = 0;                                                                  \
} while (0)

#define EVAL(_p, _nn) do {                                                    \
    int p_ = (_p);                                                            \
    float4 A = sp[p_ * 2];                                                    \
    float4 B = sp[p_ * 2 + 1];                                                \
    float n = (_nn);                                                          \
    float acc = fmaf(A.x, q0, fmaf(A.y, q1, fmaf(A.z, q2, fmaf(A.w, q3,       \
                fmaf(B.x, q4, fmaf(B.y, q5, fmaf(B.z, q6, fmaf(B.w, q7, n))))))));\
    if (acc > thr) {                                                          \
        mybuf[cnt] = (((ull)(unsigned)(tb + p_)) << 32) | (ull)__float_as_uint(acc); \
        ++cnt;                                                                \
    }                                                                         \
} while (0)

__global__ void __launch_bounds__(256) k_knn() {
    __shared__ __align__(16) char sbuf[KNN_SMEM];
    float4* sp  = (float4*)sbuf;                 // phase A: 512 points x 32B
    float*  snm = (float*)(sbuf + 16384);        // phase A: 512 norms
    ull* bufall = (ull*)(sbuf + 18432);          // per-lane push stacks
    float*  msc = (float*)sbuf;                  // phase B: [32*72] floats
    int*    mix = (int*)(sbuf + 9216);           // phase B: [32*72] ints

    int t = threadIdx.x;
    int w = t >> 5, lane = t & 31;
    int qb = blockIdx.x * QB;
    int gq = qb + lane;

    ull* mybuf = bufall + t * BCAP;
    int cnt = 0;

    float4 qa = ((const float4*)g_h2)[gq * 2];
    float4 qc = ((const float4*)g_h2)[gq * 2 + 1];
    float q0 = qa.x, q1 = qa.y, q2 = qa.z, q3 = qa.w;
    float q4 = qc.x, q5 = qc.y, q6 = qc.z, q7 = qc.w;

    float s0 = -INFINITY, s1 = -INFINITY, s2 = -INFINITY, s3 = -INFINITY,
          s4 = -INFINITY, s5 = -INFINITY, s6 = -INFINITY, s7 = -INFINITY,
          s8 = -INFINITY;
    int i0 = 0, i1 = 0, i2 = 0, i3 = 0, i4 = 0, i5 = 0, i6 = 0, i7 = 0, i8 = 0;
    float thr = -INFINITY;

    for (int tb = 0; tb < NN; tb += KT) {
        __syncthreads();
        for (int v = t; v < KT; v += 256) {
            float4 a = ((const float4*)g_h2)[(tb + v) * 2];
            float4 b = ((const float4*)g_h2)[(tb + v) * 2 + 1];
            sp[v * 2] = a; sp[v * 2 + 1] = b;
            float sq = a.x * a.x + a.y * a.y + a.z * a.z + a.w * a.w +
                       b.x * b.x + b.y * b.y + b.z * b.z + b.w * b.w;
            snm[v] = -0.5f * sq;
        }
        __syncthreads();
        int base = w << 6;   // this warp's 64-point slice
#pragma unroll 4
        for (int g = 0; g < 16; ++g) {
            int p = base + (g << 2);
            float4 nq = *(const float4*)(snm + p);
            EVAL(p + 0, nq.x);
            EVAL(p + 1, nq.y);
            EVAL(p + 2, nq.z);
            EVAL(p + 3, nq.w);
            if (__any_sync(0xffffffffu, cnt >= 9)) { DRAIN(); }
        }
    }
    DRAIN();   // flush remaining candidates

    __syncthreads();
    {
        int b = lane * 72 + w * 9;
        msc[b + 0] = s0; msc[b + 1] = s1; msc[b + 2] = s2; msc[b + 3] = s3;
        msc[b + 4] = s4; msc[b + 5] = s5; msc[b + 6] = s6; msc[b + 7] = s7;
        msc[b + 8] = s8;
        mix[b + 0] = i0; mix[b + 1] = i1; mix[b + 2] = i2; mix[b + 3] = i3;
        mix[b + 4] = i4; mix[b + 5] = i5; mix[b + 6] = i6; mix[b + 7] = i7;
        mix[b + 8] = i8;
    }
    __syncthreads();

    if (t < QB) {
        // select top-8 of 72 candidates for query qb+t (score desc, idx asc),
        // skipping self (the global max, present exactly once). No duplicates.
        int q = qb + t;
        int written = 0;
        for (int pick = 0; pick < 9 && written < 8; ++pick) {
            float bs = -INFINITY; int bi = 0x7fffffff; int bp = 0;
            for (int e = 0; e < 72; ++e) {
                float v = msc[t * 72 + e]; int id = mix[t * 72 + e];
                if (v > bs || (v == bs && id < bi)) { bs = v; bi = id; bp = e; }
            }
            msc[t * 72 + bp] = -INFINITY;
            if (bi != q) { g_knn[q * 8 + written] = bi; ++written; }
        }
    }
}

// ---------------- conv3: h2[N,8] -> h3[N,8] over kNN edges (16->8 relu ->8) --
__global__ void k_conv3(const float* __restrict__ w1, const float* __restrict__ b1,
                        const float* __restrict__ w2, const float* __restrict__ b2) {
    __shared__ float sw1[128], sb1[8], sw2[64], sb2[8];
    int t = threadIdx.x;
    for (int v = t; v < 128; v += blockDim.x) sw1[v] = w1[v];
    for (int v = t; v < 64;  v += blockDim.x) sw2[v] = w2[v];
    if (t < 8) { sb1[t] = b1[t]; sb2[t] = b2[t]; }
    __syncthreads();
    int i = blockIdx.x * blockDim.x + t;
    float xi[8];
    {
        float4 a = ((const float4*)g_h2)[i * 2];
        float4 b = ((const float4*)g_h2)[i * 2 + 1];
        xi[0] = a.x; xi[1] = a.y; xi[2] = a.z; xi[3] = a.w;
        xi[4] = b.x; xi[5] = b.y; xi[6] = b.z; xi[7] = b.w;
    }
    float out[8];
#pragma unroll
    for (int o = 0; o < 8; ++o) out[o] = 0.0f;
#pragma unroll
    for (int n = 0; n < 8; ++n) {
        int j = g_knn[i * 8 + n];
        float4 c = ((const float4*)g_h2)[j * 2];
        float4 d = ((const float4*)g_h2)[j * 2 + 1];
        float xj[8] = { c.x, c.y, c.z, c.w, d.x, d.y, d.z, d.w };
        float h[8];
#pragma unroll
        for (int o = 0; o < 8; ++o) h[o] = sb1[o];
#pragma unroll
        for (int f = 0; f < 8; ++f) {
            float m0 = xi[f], m1 = xj[f] - xi[f];
#pragma unroll
            for (int o = 0; o < 8; ++o)
                h[o] += m0 * sw1[f * 8 + o] + m1 * sw1[(8 + f) * 8 + o];
        }
#pragma unroll
        for (int o = 0; o < 8; ++o) h[o] = fmaxf(h[o], 0.0f);
#pragma unroll
        for (int o = 0; o < 8; ++o) {
            float v = sb2[o];
#pragma unroll
            for (int f = 0; f < 8; ++f) v += h[f] * sw2[f * 8 + o];
            out[o] = fmaxf(out[o], v);
        }
    }
#pragma unroll
    for (int o = 0; o < 8; ++o) g_h3[i * 8 + o] = out[o];
}

// ---------------- conv4: h3[N,8] -> h4[N,16] over kNN edges (16->16 relu ->16)
__global__ void k_conv4(const float* __restrict__ w1, const float* __restrict__ b1,
                        const float* __restrict__ w2, const float* __restrict__ b2) {
    __shared__ float sw1[256], sb1[16], sw2[256], sb2[16];
    int t = threadIdx.x;
    for (int v = t; v < 256; v += blockDim.x) { sw1[v] = w1[v]; sw2[v] = w2[v]; }
    if (t < 16) { sb1[t] = b1[t]; sb2[t] = b2[t]; }
    __syncthreads();
    int i = blockIdx.x * blockDim.x + t;
    float xi[8];
    {
        float4 a = ((const float4*)g_h3)[i * 2];
        float4 b = ((const float4*)g_h3)[i * 2 + 1];
        xi[0] = a.x; xi[1] = a.y; xi[2] = a.z; xi[3] = a.w;
        xi[4] = b.x; xi[5] = b.y; xi[6] = b.z; xi[7] = b.w;
    }
    float out[16];
#pragma unroll
    for (int o = 0; o < 16; ++o) out[o] = 0.0f;
#pragma unroll
    for (int n = 0; n < 8; ++n) {
        int j = g_knn[i * 8 + n];
        float4 c = ((const float4*)g_h3)[j * 2];
        float4 d = ((const float4*)g_h3)[j * 2 + 1];
        float xj[8] = { c.x, c.y, c.z, c.w, d.x, d.y, d.z, d.w };
        float h[16];
#pragma unroll
        for (int o = 0; o < 16; ++o) h[o] = sb1[o];
#pragma unroll
        for (int f = 0; f < 8; ++f) {
            float m0 = xi[f], m1 = xj[f] - xi[f];
#pragma unroll
            for (int o = 0; o < 16; ++o)
                h[o] += m0 * sw1[f * 16 + o] + m1 * sw1[(8 + f) * 16 + o];
        }
#pragma unroll
        for (int o = 0; o < 16; ++o) h[o] = fmaxf(h[o], 0.0f);
#pragma unroll
        for (int o = 0; o < 16; ++o) {
            float v = sb2[o];
#pragma unroll
            for (int f = 0; f < 16; ++f) v += h[f] * sw2[f * 16 + o];
            out[o] = fmaxf(out[o], v);
        }
    }
#pragma unroll
    for (int o = 0; o < 16; ++o) g_h4[i * 16 + o] = out[o];
}

// ---------------- global max pool + MLP head + sigmoid -----------------------
__global__ void k_pool(const float* __restrict__ fw, const float* __restrict__ fb,
                       const float* __restrict__ ow, const float* __restrict__ ob,
                       float* __restrict__ out) {
    __shared__ float s[128 * 16];
    int g = blockIdx.x, t = threadIdx.x;
    int node = g * 128 + t;
#pragma unroll
    for (int f = 0; f < 16; ++f) s[t * 16 + f] = g_h4[node * 16 + f];
    __syncthreads();
    for (int st = 64; st > 0; st >>= 1) {
        if (t < st) {
#pragma unroll
            for (int f = 0; f < 16; ++f)
                s[t * 16 + f] = fmaxf(s[t * 16 + f], s[(t + st) * 16 + f]);
        }
        __syncthreads();
    }
    if (t == 0) {
        float z = ob[0];
#pragma unroll
        for (int o = 0; o < 6; ++o) {
            float y = fb[o];
#pragma unroll
            for (int f = 0; f < 16; ++f) y += s[f] * fw[f * 6 + o];
            z += fmaxf(y, 0.0f) * ow[o];
        }
        out[g] = 1.0f / (1.0f + expf(-z));
    }
}

// ---------------- launch ------------------------------------------------------
extern "C" void kernel_launch(void* const* d_in, const int* in_sizes, int n_in,
                              void* d_out, int out_size) {
    const float* x    = (const float*)d_in[0];
    const int*   ei   = (const int*)d_in[1];
    const float* c1w1 = (const float*)d_in[3];
    const float* c1b1 = (const float*)d_in[4];
    const float* c1w2 = (const float*)d_in[5];
    const float* c1b2 = (const float*)d_in[6];
    const float* c2w1 = (const float*)d_in[7];
    const float* c2b1 = (const float*)d_in[8];
    const float* c2w2 = (const float*)d_in[9];
    const float* c2b2 = (const float*)d_in[10];
    const float* c3w1 = (const float*)d_in[11];
    const float* c3b1 = (const float*)d_in[12];
    const float* c3w2 = (const float*)d_in[13];
    const float* c3b2 = (const float*)d_in[14];
    const float* c4w1 = (const float*)d_in[15];
    const float* c4b1 = (const float*)d_in[16];
    const float* c4w2 = (const float*)d_in[17];
    const float* c4b2 = (const float*)d_in[18];
    const float* fc3w = (const float*)d_in[19];
    const float* fc3b = (const float*)d_in[20];
    const float* outw = (const float*)d_in[21];
    const float* outb = (const float*)d_in[22];

    k_init <<< (NN * 16 + 255) / 256, 256 >>> ();
    k_conv1<<< E0C / 256, 256 >>>(x, ei, c1w1, c1b1, c1w2, c1b2);
    k_conv2<<< E0C / 256, 256 >>>(ei, c2w1, c2b1, c2w2, c2b2);
    k_knn  <<< NN / QB, 256 >>>();
    k_conv3<<< NN / 128, 128 >>>(c3w1, c3b1, c3w2, c3b2);
    k_conv4<<< NN / 128, 128 >>>(c4w1, c4b1, c4w2, c4b2);
    k_pool <<< GG, 128 >>>(fc3w, fc3b, outw, outb, (float*)d_out);
}